// round 13
// baseline (speedup 1.0000x reference)
#include <cuda_runtime.h>
#include <cstdint>
#include <cstddef>

// ---------------------------------------------------------------------------
// NSHE: 3 per-type linear encoders (+ReLU)  ->  GCN linear  ->  edge
// gather*weight scatter-add (segment_sum)   ->  row L2-normalize.
// GEMMs use tf32 tensor cores (mma.sync m16n8k8), accumulate fp32.
// Scratch lives in __device__ globals (no allocation).
// ---------------------------------------------------------------------------

#define NMAX 200000
#define D 64

__device__ float g_enc[(size_t)NMAX * D];
__device__ float g_support[(size_t)NMAX * D];

// ---- tf32 helpers ---------------------------------------------------------
__device__ __forceinline__ float tf32_rna(float x) {
    unsigned u;
    asm("cvt.rna.tf32.f32 %0, %1;" : "=r"(u) : "f"(x));
    return __uint_as_float(u);
}

__device__ __forceinline__ void mma_tf32(float* c, const unsigned* a,
                                         const unsigned* b) {
    asm volatile(
        "mma.sync.aligned.m16n8k8.row.col.f32.tf32.tf32.f32 "
        "{%0,%1,%2,%3}, {%4,%5,%6,%7}, {%8,%9}, {%0,%1,%2,%3};"
        : "+f"(c[0]), "+f"(c[1]), "+f"(c[2]), "+f"(c[3])
        : "r"(a[0]), "r"(a[1]), "r"(a[2]), "r"(a[3]), "r"(b[0]), "r"(b[1]));
}

// ---------------------------------------------------------------------------
// GEMM: out[n,64] = act(A[n,K] @ W[K,64] + bias), tf32 tensor cores.
// Block tile 256(M) x 64(N), BK=32, 256 threads = 8 warps.
// Warp tile 32(M) x 64(N) = 2 m16-subtiles x 8 n8-subtiles of m16n8k8.
// ---------------------------------------------------------------------------
template <int K, bool RELU>
__global__ void __launch_bounds__(256, 2)
gemm_tc(const float* __restrict__ A, const float* __restrict__ W,
        const float* __restrict__ bias, float* __restrict__ out, int nRows)
{
    constexpr int BM = 256;
    constexpr int BK = 32;
    __shared__ float sA[BM][BK + 4];   // pad 36: frag reads conflict-free
    __shared__ float sB[BK][64 + 8];   // pad 72: stride%32==8 -> conflict-free

    const int t    = threadIdx.x;
    const int warp = t >> 5;
    const int lane = t & 31;
    const int row0 = blockIdx.x * BM;
    const int wrow = warp * 32;

    const int g4 = lane >> 2;  // groupID       (0..7)
    const int t4 = lane & 3;   // thread-in-grp (0..3)

    float acc[2][8][4];
#pragma unroll
    for (int mt = 0; mt < 2; mt++)
#pragma unroll
        for (int nt = 0; nt < 8; nt++)
#pragma unroll
            for (int i = 0; i < 4; i++) acc[mt][nt][i] = 0.f;

    for (int k0 = 0; k0 < K; k0 += BK) {
        // ---- load A tile: 256 rows x 32 cols = 2048 float4 ----
#pragma unroll
        for (int i = 0; i < 8; i++) {
            int idx = t + i * 256;
            int r   = idx >> 3;        // 0..255
            int f   = idx & 7;         // float4 slot 0..7
            int gr  = row0 + r;
            float4 v = make_float4(0.f, 0.f, 0.f, 0.f);
            if (gr < nRows)
                v = *reinterpret_cast<const float4*>(A + (size_t)gr * K + k0 + f * 4);
            sA[r][f * 4 + 0] = tf32_rna(v.x);
            sA[r][f * 4 + 1] = tf32_rna(v.y);
            sA[r][f * 4 + 2] = tf32_rna(v.z);
            sA[r][f * 4 + 3] = tf32_rna(v.w);
        }
        // ---- load B tile: 32 x 64 = 512 float4 ----
#pragma unroll
        for (int i = 0; i < 2; i++) {
            int idx = t + i * 256;
            int kk  = idx >> 4;        // 0..31
            int f   = idx & 15;        // 0..15
            float4 v = *reinterpret_cast<const float4*>(W + (size_t)(k0 + kk) * 64 + f * 4);
            sB[kk][f * 4 + 0] = tf32_rna(v.x);
            sB[kk][f * 4 + 1] = tf32_rna(v.y);
            sB[kk][f * 4 + 2] = tf32_rna(v.z);
            sB[kk][f * 4 + 3] = tf32_rna(v.w);
        }
        __syncthreads();

#pragma unroll
        for (int k8 = 0; k8 < BK / 8; k8++) {
            unsigned bf[8][2];
#pragma unroll
            for (int nt = 0; nt < 8; nt++) {
                bf[nt][0] = __float_as_uint(sB[k8 * 8 + t4    ][nt * 8 + g4]);
                bf[nt][1] = __float_as_uint(sB[k8 * 8 + t4 + 4][nt * 8 + g4]);
            }
#pragma unroll
            for (int mt = 0; mt < 2; mt++) {
                unsigned af[4];
                int r = wrow + mt * 16 + g4;
                af[0] = __float_as_uint(sA[r    ][k8 * 8 + t4    ]);
                af[1] = __float_as_uint(sA[r + 8][k8 * 8 + t4    ]);
                af[2] = __float_as_uint(sA[r    ][k8 * 8 + t4 + 4]);
                af[3] = __float_as_uint(sA[r + 8][k8 * 8 + t4 + 4]);
#pragma unroll
                for (int nt = 0; nt < 8; nt++)
                    mma_tf32(acc[mt][nt], af, bf[nt]);
            }
        }
        __syncthreads();
    }

    // ---- epilogue: + bias, optional relu, float2 stores ----
#pragma unroll
    for (int nt = 0; nt < 8; nt++) {
        int col  = nt * 8 + 2 * t4;
        float b0 = bias[col];
        float b1 = bias[col + 1];
#pragma unroll
        for (int mt = 0; mt < 2; mt++) {
#pragma unroll
            for (int h = 0; h < 2; h++) {
                int gr = row0 + wrow + mt * 16 + g4 + h * 8;
                if (gr < nRows) {
                    float x0 = acc[mt][nt][h * 2 + 0] + b0;
                    float x1 = acc[mt][nt][h * 2 + 1] + b1;
                    if (RELU) {
                        x0 = fmaxf(x0, 0.f);
                        x1 = fmaxf(x1, 0.f);
                    }
                    *reinterpret_cast<float2*>(out + (size_t)gr * 64 + col) =
                        make_float2(x0, x1);
                }
            }
        }
    }
}

// ---------------------------------------------------------------------------
// Edge scatter: out[dst] += support[src] * w, 16 threads per edge (float4 each).
// support (51 MB) and out (51 MB) are both L2-resident. Vector atomics cut
// L2 atomic op count 4x vs scalar atomicAdd.
// ---------------------------------------------------------------------------
__global__ void __launch_bounds__(256)
edge_kernel(const float* __restrict__ support, const int* __restrict__ src,
            const int* __restrict__ dst, const float* __restrict__ w,
            float* __restrict__ out, int E)
{
    int g   = blockIdx.x * 256 + threadIdx.x;
    int e   = g >> 4;
    int sub = g & 15;
    if (e >= E) return;
    int   s  = src[e];
    int   d  = dst[e];
    float wt = w[e];
    float4 v = *reinterpret_cast<const float4*>(support + (size_t)s * 64 + sub * 4);
    float* o = out + (size_t)d * 64 + sub * 4;
    asm volatile("red.global.add.v4.f32 [%0], {%1, %2, %3, %4};"
                 :: "l"(o), "f"(v.x * wt), "f"(v.y * wt),
                    "f"(v.z * wt), "f"(v.w * wt)
                 : "memory");
}

// ---------------------------------------------------------------------------
__global__ void __launch_bounds__(256)
zero_kernel(float4* __restrict__ out, int n4)
{
    int i = blockIdx.x * 256 + threadIdx.x;
    if (i < n4) out[i] = make_float4(0.f, 0.f, 0.f, 0.f);
}

// warp per row: L2-normalize rows of 64 (matches jnp: row / max(||row||, 1e-12))
__global__ void __launch_bounds__(256)
normalize_kernel(float* __restrict__ out, int N)
{
    int row  = blockIdx.x * 8 + (threadIdx.x >> 5);
    int lane = threadIdx.x & 31;
    if (row >= N) return;
    float* p = out + (size_t)row * 64;
    float2 v = *reinterpret_cast<float2*>(p + lane * 2);
    float ss = v.x * v.x + v.y * v.y;
#pragma unroll
    for (int o = 16; o > 0; o >>= 1) ss += __shfl_xor_sync(0xFFFFFFFFu, ss, o);
    float inv = 1.0f / fmaxf(sqrtf(ss), 1e-12f);
    v.x *= inv;
    v.y *= inv;
    *reinterpret_cast<float2*>(p + lane * 2) = v;
}

// ---------------------------------------------------------------------------
extern "C" void kernel_launch(void* const* d_in, const int* in_sizes, int n_in,
                              void* d_out, int out_size)
{
    const float* feat_a   = (const float*)d_in[0];
    const float* W_a      = (const float*)d_in[1];
    const float* b_a      = (const float*)d_in[2];
    const float* feat_b   = (const float*)d_in[3];
    const float* W_b      = (const float*)d_in[4];
    const float* b_b      = (const float*)d_in[5];
    const float* feat_c   = (const float*)d_in[6];
    const float* W_c      = (const float*)d_in[7];
    const float* b_c      = (const float*)d_in[8];
    const float* gcn_W    = (const float*)d_in[9];
    const float* gcn_b    = (const float*)d_in[10];
    const float* edge_w   = (const float*)d_in[11];
    const int*   edge_src = (const int*)d_in[12];
    const int*   edge_dst = (const int*)d_in[13];

    const int nA = in_sizes[0] / 512;
    const int nB = in_sizes[3] / 256;
    const int nC = in_sizes[6] / 128;
    const int N  = nA + nB + nC;
    const int E  = in_sizes[11];

    float* enc = nullptr;
    float* sup = nullptr;
    cudaGetSymbolAddress((void**)&enc, g_enc);
    cudaGetSymbolAddress((void**)&sup, g_support);

    float* out = (float*)d_out;

    // zero the accumulator (d_out is poisoned)
    {
        int n4 = N * 16;
        zero_kernel<<<(n4 + 255) / 256, 256>>>((float4*)out, n4);
    }

    // per-type encoders -> g_enc (relu), tf32 tensor cores
    gemm_tc<512, true><<<(nA + 255) / 256, 256>>>(feat_a, W_a, b_a, enc, nA);
    gemm_tc<256, true><<<(nB + 255) / 256, 256>>>(feat_b, W_b, b_b,
                                                  enc + (size_t)nA * 64, nB);
    gemm_tc<128, true><<<(nC + 255) / 256, 256>>>(feat_c, W_c, b_c,
                                                  enc + (size_t)(nA + nB) * 64, nC);

    // GCN linear: support = enc @ gcn_W + gcn_b
    gemm_tc<64, false><<<(N + 255) / 256, 256>>>(enc, gcn_W, gcn_b, sup, N);

    // edge gather/scale/scatter-add into out
    {
        long long tot = (long long)E * 16;
        int blocks = (int)((tot + 255) / 256);
        edge_kernel<<<blocks, 256>>>(sup, edge_src, edge_dst, edge_w, out, E);
    }

    // row-wise L2 normalize in place
    normalize_kernel<<<(N + 7) / 8, 256>>>(out, N);
}

// round 14
// speedup vs baseline: 1.1871x; 1.1871x over previous
#include <cuda_runtime.h>
#include <cstdint>
#include <cstddef>

// ---------------------------------------------------------------------------
// NSHE fused: per-type encoder GEMM (relu(feat@W+b)) FUSED with GCN linear
// (@gcn_W + gcn_b) in one kernel -> g_support. Then edge gather*w scatter-add
// (L2 vector atomics) -> row L2-normalize.
// GEMM stage-1: tf32 mma.sync m16n8k8, cp.async double-buffered pipeline.
// GEMM stage-2: block-local 256x64 @ 64x64 from smem (weights tf32 in smem).
// ---------------------------------------------------------------------------

#define NMAX 200000

__device__ float g_support[(size_t)NMAX * 64];

// ---- helpers --------------------------------------------------------------
__device__ __forceinline__ unsigned tf32u(float x) {
    unsigned u;
    asm("cvt.rna.tf32.f32 %0, %1;" : "=r"(u) : "f"(x));
    return u;
}
__device__ __forceinline__ float tf32f(float x) {
    return __uint_as_float(tf32u(x));
}

__device__ __forceinline__ void mma_tf32(float* c, const unsigned* a,
                                         const unsigned* b) {
    asm volatile(
        "mma.sync.aligned.m16n8k8.row.col.f32.tf32.tf32.f32 "
        "{%0,%1,%2,%3}, {%4,%5,%6,%7}, {%8,%9}, {%0,%1,%2,%3};"
        : "+f"(c[0]), "+f"(c[1]), "+f"(c[2]), "+f"(c[3])
        : "r"(a[0]), "r"(a[1]), "r"(a[2]), "r"(a[3]), "r"(b[0]), "r"(b[1]));
}

__device__ __forceinline__ void cp16(uint32_t dst, const void* src, bool p) {
    int sz = p ? 16 : 0;
    asm volatile("cp.async.cg.shared.global [%0], [%1], 16, %2;"
                 :: "r"(dst), "l"(src), "r"(sz));
}

// ---------------------------------------------------------------------------
// Fused encoder + GCN. Block tile 256(M) x 64(N), BK=32, 256 thr = 8 warps.
// Warp tile 32x64 = 2 m16 x 8 n8 subtiles of m16n8k8 tf32.
// Dynamic smem (92160 B):
//   stage 1: sA[2][256][36] (raw fp32 via cp.async), sB[2][32][72]
//   stage 2 (aliased): sE[256][68] (relu'd enc, tf32), sW2[64][72] (gcn_W tf32)
// ---------------------------------------------------------------------------
template <int K>
__global__ void __launch_bounds__(256, 2)
fused_enc_gcn(const float* __restrict__ A, const float* __restrict__ W1,
              const float* __restrict__ b1, const float* __restrict__ gW,
              const float* __restrict__ gb, float* __restrict__ out, int nRows)
{
    extern __shared__ float smem[];
    float* sA = smem;            // 2 * 256 * 36 = 18432 floats
    float* sB = smem + 18432;    // 2 *  32 * 72 =  4608 floats

    const int t    = threadIdx.x;
    const int warp = t >> 5;
    const int lane = t & 31;
    const int row0 = blockIdx.x * 256;
    const int wrow = warp * 32;
    const int g4   = lane >> 2;
    const int t4   = lane & 3;

    const uint32_t sA_u = (uint32_t)__cvta_generic_to_shared(sA);
    const uint32_t sB_u = (uint32_t)__cvta_generic_to_shared(sB);

    float acc[2][8][4];
#pragma unroll
    for (int mt = 0; mt < 2; mt++)
#pragma unroll
        for (int nt = 0; nt < 8; nt++)
#pragma unroll
            for (int i = 0; i < 4; i++) acc[mt][nt][i] = 0.f;

    auto load_tiles = [&](int buf, int k0) {
#pragma unroll
        for (int i = 0; i < 8; i++) {
            int idx = t + i * 256;
            int r   = idx >> 3;
            int f   = idx & 7;
            int gr  = row0 + r;
            bool ok = gr < nRows;
            const float* src = A + (size_t)(ok ? gr : 0) * K + k0 + f * 4;
            cp16(sA_u + (uint32_t)(buf * 9216 + r * 36 + f * 4) * 4, src, ok);
        }
#pragma unroll
        for (int i = 0; i < 2; i++) {
            int idx = t + i * 256;
            int kk  = idx >> 4;
            int f   = idx & 15;
            cp16(sB_u + (uint32_t)(buf * 2304 + kk * 72 + f * 4) * 4,
                 W1 + (size_t)(k0 + kk) * 64 + f * 4, true);
        }
        asm volatile("cp.async.commit_group;");
    };

    constexpr int NIT = K / 32;
    load_tiles(0, 0);

    for (int it = 0; it < NIT; ++it) {
        if (it + 1 < NIT)
            load_tiles((it + 1) & 1, (it + 1) * 32);
        else
            asm volatile("cp.async.commit_group;");
        asm volatile("cp.async.wait_group 1;");
        __syncthreads();

        const float* bA = sA + (it & 1) * 9216;
        const float* bB = sB + (it & 1) * 2304;
#pragma unroll
        for (int k8 = 0; k8 < 4; k8++) {
            unsigned bf[8][2];
#pragma unroll
            for (int nt = 0; nt < 8; nt++) {
                bf[nt][0] = tf32u(bB[(k8 * 8 + t4    ) * 72 + nt * 8 + g4]);
                bf[nt][1] = tf32u(bB[(k8 * 8 + t4 + 4) * 72 + nt * 8 + g4]);
            }
#pragma unroll
            for (int mt = 0; mt < 2; mt++) {
                int r = wrow + mt * 16 + g4;
                unsigned af[4];
                af[0] = tf32u(bA[(r    ) * 36 + k8 * 8 + t4    ]);
                af[1] = tf32u(bA[(r + 8) * 36 + k8 * 8 + t4    ]);
                af[2] = tf32u(bA[(r    ) * 36 + k8 * 8 + t4 + 4]);
                af[3] = tf32u(bA[(r + 8) * 36 + k8 * 8 + t4 + 4]);
#pragma unroll
                for (int nt = 0; nt < 8; nt++)
                    mma_tf32(acc[mt][nt], af, bf[nt]);
            }
        }
        __syncthreads();
    }

    // ---- stage 2 setup: relu(acc+b1) -> sE (tf32), gcn_W -> sW2 (tf32) ----
    float* sE  = smem;           // [256][68]
    float* sW2 = smem + 18432;   // [64][72]

#pragma unroll
    for (int nt = 0; nt < 8; nt++) {
        int col   = nt * 8 + 2 * t4;
        float bb0 = b1[col];
        float bb1 = b1[col + 1];
#pragma unroll
        for (int mt = 0; mt < 2; mt++)
#pragma unroll
            for (int h = 0; h < 2; h++) {
                int r = wrow + mt * 16 + h * 8 + g4;
                float x0 = fmaxf(acc[mt][nt][h * 2 + 0] + bb0, 0.f);
                float x1 = fmaxf(acc[mt][nt][h * 2 + 1] + bb1, 0.f);
                *reinterpret_cast<float2*>(&sE[r * 68 + col]) =
                    make_float2(tf32f(x0), tf32f(x1));
            }
    }
#pragma unroll
    for (int i = 0; i < 4; i++) {
        int idx = t + i * 256;   // 0..1023
        int kk  = idx >> 4;
        int f   = idx & 15;
        float4 v = *reinterpret_cast<const float4*>(gW + (size_t)kk * 64 + f * 4);
        sW2[kk * 72 + f * 4 + 0] = tf32f(v.x);
        sW2[kk * 72 + f * 4 + 1] = tf32f(v.y);
        sW2[kk * 72 + f * 4 + 2] = tf32f(v.z);
        sW2[kk * 72 + f * 4 + 3] = tf32f(v.w);
    }
    __syncthreads();

    // ---- stage 2 MMA: 256x64 @ 64x64 ----
    float acc2[2][8][4];
#pragma unroll
    for (int mt = 0; mt < 2; mt++)
#pragma unroll
        for (int nt = 0; nt < 8; nt++)
#pragma unroll
            for (int i = 0; i < 4; i++) acc2[mt][nt][i] = 0.f;

#pragma unroll
    for (int k8 = 0; k8 < 8; k8++) {
        unsigned bf[8][2];
#pragma unroll
        for (int nt = 0; nt < 8; nt++) {
            bf[nt][0] = __float_as_uint(sW2[(k8 * 8 + t4    ) * 72 + nt * 8 + g4]);
            bf[nt][1] = __float_as_uint(sW2[(k8 * 8 + t4 + 4) * 72 + nt * 8 + g4]);
        }
#pragma unroll
        for (int mt = 0; mt < 2; mt++) {
            int r = wrow + mt * 16 + g4;
            unsigned af[4];
            af[0] = __float_as_uint(sE[(r    ) * 68 + k8 * 8 + t4    ]);
            af[1] = __float_as_uint(sE[(r + 8) * 68 + k8 * 8 + t4    ]);
            af[2] = __float_as_uint(sE[(r    ) * 68 + k8 * 8 + t4 + 4]);
            af[3] = __float_as_uint(sE[(r + 8) * 68 + k8 * 8 + t4 + 4]);
#pragma unroll
            for (int nt = 0; nt < 8; nt++)
                mma_tf32(acc2[mt][nt], af, bf[nt]);
        }
    }

    // ---- epilogue: + gcn_b, store support ----
#pragma unroll
    for (int nt = 0; nt < 8; nt++) {
        int col   = nt * 8 + 2 * t4;
        float bb0 = gb[col];
        float bb1 = gb[col + 1];
#pragma unroll
        for (int mt = 0; mt < 2; mt++)
#pragma unroll
            for (int h = 0; h < 2; h++) {
                int gr = row0 + wrow + mt * 16 + h * 8 + g4;
                if (gr < nRows) {
                    *reinterpret_cast<float2*>(out + (size_t)gr * 64 + col) =
                        make_float2(acc2[mt][nt][h * 2 + 0] + bb0,
                                    acc2[mt][nt][h * 2 + 1] + bb1);
                }
            }
    }
}

// ---------------------------------------------------------------------------
// Edge scatter: out[dst] += support[src] * w, 16 threads/edge (float4 each).
// support (51 MB) + out (51 MB) are L2-resident; v4 red cuts atomic op count.
// ---------------------------------------------------------------------------
__global__ void __launch_bounds__(256)
edge_kernel(const float* __restrict__ support, const int* __restrict__ src,
            const int* __restrict__ dst, const float* __restrict__ w,
            float* __restrict__ out, int E)
{
    int g   = blockIdx.x * 256 + threadIdx.x;
    int e   = g >> 4;
    int sub = g & 15;
    if (e >= E) return;
    int   s  = src[e];
    int   d  = dst[e];
    float wt = w[e];
    float4 v = *reinterpret_cast<const float4*>(support + (size_t)s * 64 + sub * 4);
    float* o = out + (size_t)d * 64 + sub * 4;
    asm volatile("red.global.add.v4.f32 [%0], {%1, %2, %3, %4};"
                 :: "l"(o), "f"(v.x * wt), "f"(v.y * wt),
                    "f"(v.z * wt), "f"(v.w * wt)
                 : "memory");
}

// ---------------------------------------------------------------------------
__global__ void __launch_bounds__(256)
zero_kernel(float4* __restrict__ out, int n4)
{
    int i = blockIdx.x * 256 + threadIdx.x;
    if (i < n4) out[i] = make_float4(0.f, 0.f, 0.f, 0.f);
}

__global__ void __launch_bounds__(256)
normalize_kernel(float* __restrict__ out, int N)
{
    int row  = blockIdx.x * 8 + (threadIdx.x >> 5);
    int lane = threadIdx.x & 31;
    if (row >= N) return;
    float* p = out + (size_t)row * 64;
    float2 v = *reinterpret_cast<float2*>(p + lane * 2);
    float ss = v.x * v.x + v.y * v.y;
#pragma unroll
    for (int o = 16; o > 0; o >>= 1) ss += __shfl_xor_sync(0xFFFFFFFFu, ss, o);
    float inv = 1.0f / fmaxf(sqrtf(ss), 1e-12f);
    v.x *= inv;
    v.y *= inv;
    *reinterpret_cast<float2*>(p + lane * 2) = v;
}

// ---------------------------------------------------------------------------
extern "C" void kernel_launch(void* const* d_in, const int* in_sizes, int n_in,
                              void* d_out, int out_size)
{
    const float* feat_a   = (const float*)d_in[0];
    const float* W_a      = (const float*)d_in[1];
    const float* b_a      = (const float*)d_in[2];
    const float* feat_b   = (const float*)d_in[3];
    const float* W_b      = (const float*)d_in[4];
    const float* b_b      = (const float*)d_in[5];
    const float* feat_c   = (const float*)d_in[6];
    const float* W_c      = (const float*)d_in[7];
    const float* b_c      = (const float*)d_in[8];
    const float* gcn_W    = (const float*)d_in[9];
    const float* gcn_b    = (const float*)d_in[10];
    const float* edge_w   = (const float*)d_in[11];
    const int*   edge_src = (const int*)d_in[12];
    const int*   edge_dst = (const int*)d_in[13];

    const int nA = in_sizes[0] / 512;
    const int nB = in_sizes[3] / 256;
    const int nC = in_sizes[6] / 128;
    const int N  = nA + nB + nC;
    const int E  = in_sizes[11];

    float* sup = nullptr;
    cudaGetSymbolAddress((void**)&sup, g_support);
    float* out = (float*)d_out;

    const int SMEM = 92160;
    cudaFuncSetAttribute(fused_enc_gcn<512>,
                         cudaFuncAttributeMaxDynamicSharedMemorySize, SMEM);
    cudaFuncSetAttribute(fused_enc_gcn<256>,
                         cudaFuncAttributeMaxDynamicSharedMemorySize, SMEM);
    cudaFuncSetAttribute(fused_enc_gcn<128>,
                         cudaFuncAttributeMaxDynamicSharedMemorySize, SMEM);

    // zero the accumulator (d_out is poisoned)
    {
        int n4 = N * 16;
        zero_kernel<<<(n4 + 255) / 256, 256>>>((float4*)out, n4);
    }

    // fused encoder + GCN -> g_support
    fused_enc_gcn<512><<<(nA + 255) / 256, 256, SMEM>>>(
        feat_a, W_a, b_a, gcn_W, gcn_b, sup, nA);
    fused_enc_gcn<256><<<(nB + 255) / 256, 256, SMEM>>>(
        feat_b, W_b, b_b, gcn_W, gcn_b, sup + (size_t)nA * 64, nB);
    fused_enc_gcn<128><<<(nC + 255) / 256, 256, SMEM>>>(
        feat_c, W_c, b_c, gcn_W, gcn_b, sup + (size_t)(nA + nB) * 64, nC);

    // edge gather/scale/scatter-add into out
    {
        long long tot = (long long)E * 16;
        int blocks = (int)((tot + 255) / 256);
        edge_kernel<<<blocks, 256>>>(sup, edge_src, edge_dst, edge_w, out, E);
    }

    // row-wise L2 normalize in place
    normalize_kernel<<<(N + 7) / 8, 256>>>(out, N);
}

// round 15
// speedup vs baseline: 1.1949x; 1.0066x over previous
#include <cuda_runtime.h>
#include <cstdint>
#include <cstddef>

// ---------------------------------------------------------------------------
// NSHE fused: per-type encoder GEMM (relu(feat@W+b)) FUSED with GCN linear
// (@gcn_W + gcn_b) in one kernel -> g_support. Then edge gather*w scatter-add
// (L2 vector atomics) -> row L2-normalize.
// GEMM stage-1: tf32 mma.sync m16n8k8, cp.async double-buffered pipeline.
// GEMM stage-2: block-local 256x64 @ 64x64 from smem (weights tf32 in smem).
// ---------------------------------------------------------------------------

#define NMAX 200000

__device__ float g_support[(size_t)NMAX * 64];

// ---- helpers --------------------------------------------------------------
__device__ __forceinline__ unsigned tf32u(float x) {
    unsigned u;
    asm("cvt.rna.tf32.f32 %0, %1;" : "=r"(u) : "f"(x));
    return u;
}
__device__ __forceinline__ float tf32f(float x) {
    return __uint_as_float(tf32u(x));
}

__device__ __forceinline__ void mma_tf32(float* c, const unsigned* a,
                                         const unsigned* b) {
    asm volatile(
        "mma.sync.aligned.m16n8k8.row.col.f32.tf32.tf32.f32 "
        "{%0,%1,%2,%3}, {%4,%5,%6,%7}, {%8,%9}, {%0,%1,%2,%3};"
        : "+f"(c[0]), "+f"(c[1]), "+f"(c[2]), "+f"(c[3])
        : "r"(a[0]), "r"(a[1]), "r"(a[2]), "r"(a[3]), "r"(b[0]), "r"(b[1]));
}

__device__ __forceinline__ void cp16(uint32_t dst, const void* src, bool p) {
    int sz = p ? 16 : 0;
    asm volatile("cp.async.cg.shared.global [%0], [%1], 16, %2;"
                 :: "r"(dst), "l"(src), "r"(sz));
}

// ---------------------------------------------------------------------------
// Fused encoder + GCN. Block tile 256(M) x 64(N), BK=32, 256 thr = 8 warps.
// Warp tile 32x64 = 2 m16 x 8 n8 subtiles of m16n8k8 tf32.
// Dynamic smem (92160 B):
//   stage 1: sA[2][256][36] (raw fp32 via cp.async), sB[2][32][72]
//   stage 2 (aliased): sE[256][68] (relu'd enc, tf32), sW2[64][72] (gcn_W tf32)
// ---------------------------------------------------------------------------
template <int K>
__global__ void __launch_bounds__(256, 2)
fused_enc_gcn(const float* __restrict__ A, const float* __restrict__ W1,
              const float* __restrict__ b1, const float* __restrict__ gW,
              const float* __restrict__ gb, float* __restrict__ out, int nRows)
{
    extern __shared__ float smem[];
    float* sA = smem;            // 2 * 256 * 36 = 18432 floats
    float* sB = smem + 18432;    // 2 *  32 * 72 =  4608 floats

    const int t    = threadIdx.x;
    const int warp = t >> 5;
    const int lane = t & 31;
    const int row0 = blockIdx.x * 256;
    const int wrow = warp * 32;
    const int g4   = lane >> 2;
    const int t4   = lane & 3;

    const uint32_t sA_u = (uint32_t)__cvta_generic_to_shared(sA);
    const uint32_t sB_u = (uint32_t)__cvta_generic_to_shared(sB);

    float acc[2][8][4];
#pragma unroll
    for (int mt = 0; mt < 2; mt++)
#pragma unroll
        for (int nt = 0; nt < 8; nt++)
#pragma unroll
            for (int i = 0; i < 4; i++) acc[mt][nt][i] = 0.f;

    auto load_tiles = [&](int buf, int k0) {
#pragma unroll
        for (int i = 0; i < 8; i++) {
            int idx = t + i * 256;
            int r   = idx >> 3;
            int f   = idx & 7;
            int gr  = row0 + r;
            bool ok = gr < nRows;
            const float* src = A + (size_t)(ok ? gr : 0) * K + k0 + f * 4;
            cp16(sA_u + (uint32_t)(buf * 9216 + r * 36 + f * 4) * 4, src, ok);
        }
#pragma unroll
        for (int i = 0; i < 2; i++) {
            int idx = t + i * 256;
            int kk  = idx >> 4;
            int f   = idx & 15;
            cp16(sB_u + (uint32_t)(buf * 2304 + kk * 72 + f * 4) * 4,
                 W1 + (size_t)(k0 + kk) * 64 + f * 4, true);
        }
        asm volatile("cp.async.commit_group;");
    };

    constexpr int NIT = K / 32;
    load_tiles(0, 0);

    for (int it = 0; it < NIT; ++it) {
        if (it + 1 < NIT)
            load_tiles((it + 1) & 1, (it + 1) * 32);
        else
            asm volatile("cp.async.commit_group;");
        asm volatile("cp.async.wait_group 1;");
        __syncthreads();

        const float* bA = sA + (it & 1) * 9216;
        const float* bB = sB + (it & 1) * 2304;
#pragma unroll
        for (int k8 = 0; k8 < 4; k8++) {
            unsigned bf[8][2];
#pragma unroll
            for (int nt = 0; nt < 8; nt++) {
                bf[nt][0] = tf32u(bB[(k8 * 8 + t4    ) * 72 + nt * 8 + g4]);
                bf[nt][1] = tf32u(bB[(k8 * 8 + t4 + 4) * 72 + nt * 8 + g4]);
            }
#pragma unroll
            for (int mt = 0; mt < 2; mt++) {
                int r = wrow + mt * 16 + g4;
                unsigned af[4];
                af[0] = tf32u(bA[(r    ) * 36 + k8 * 8 + t4    ]);
                af[1] = tf32u(bA[(r + 8) * 36 + k8 * 8 + t4    ]);
                af[2] = tf32u(bA[(r    ) * 36 + k8 * 8 + t4 + 4]);
                af[3] = tf32u(bA[(r + 8) * 36 + k8 * 8 + t4 + 4]);
#pragma unroll
                for (int nt = 0; nt < 8; nt++)
                    mma_tf32(acc[mt][nt], af, bf[nt]);
            }
        }
        __syncthreads();
    }

    // ---- stage 2 setup: relu(acc+b1) -> sE (tf32), gcn_W -> sW2 (tf32) ----
    float* sE  = smem;           // [256][68]
    float* sW2 = smem + 18432;   // [64][72]

#pragma unroll
    for (int nt = 0; nt < 8; nt++) {
        int col   = nt * 8 + 2 * t4;
        float bb0 = b1[col];
        float bb1 = b1[col + 1];
#pragma unroll
        for (int mt = 0; mt < 2; mt++)
#pragma unroll
            for (int h = 0; h < 2; h++) {
                int r = wrow + mt * 16 + h * 8 + g4;
                float x0 = fmaxf(acc[mt][nt][h * 2 + 0] + bb0, 0.f);
                float x1 = fmaxf(acc[mt][nt][h * 2 + 1] + bb1, 0.f);
                *reinterpret_cast<float2*>(&sE[r * 68 + col]) =
                    make_float2(tf32f(x0), tf32f(x1));
            }
    }
#pragma unroll
    for (int i = 0; i < 4; i++) {
        int idx = t + i * 256;   // 0..1023
        int kk  = idx >> 4;
        int f   = idx & 15;
        float4 v = *reinterpret_cast<const float4*>(gW + (size_t)kk * 64 + f * 4);
        sW2[kk * 72 + f * 4 + 0] = tf32f(v.x);
        sW2[kk * 72 + f * 4 + 1] = tf32f(v.y);
        sW2[kk * 72 + f * 4 + 2] = tf32f(v.z);
        sW2[kk * 72 + f * 4 + 3] = tf32f(v.w);
    }
    __syncthreads();

    // ---- stage 2 MMA: 256x64 @ 64x64 ----
    float acc2[2][8][4];
#pragma unroll
    for (int mt = 0; mt < 2; mt++)
#pragma unroll
        for (int nt = 0; nt < 8; nt++)
#pragma unroll
            for (int i = 0; i < 4; i++) acc2[mt][nt][i] = 0.f;

#pragma unroll
    for (int k8 = 0; k8 < 8; k8++) {
        unsigned bf[8][2];
#pragma unroll
        for (int nt = 0; nt < 8; nt++) {
            bf[nt][0] = __float_as_uint(sW2[(k8 * 8 + t4    ) * 72 + nt * 8 + g4]);
            bf[nt][1] = __float_as_uint(sW2[(k8 * 8 + t4 + 4) * 72 + nt * 8 + g4]);
        }
#pragma unroll
        for (int mt = 0; mt < 2; mt++) {
            int r = wrow + mt * 16 + g4;
            unsigned af[4];
            af[0] = __float_as_uint(sE[(r    ) * 68 + k8 * 8 + t4    ]);
            af[1] = __float_as_uint(sE[(r + 8) * 68 + k8 * 8 + t4    ]);
            af[2] = __float_as_uint(sE[(r    ) * 68 + k8 * 8 + t4 + 4]);
            af[3] = __float_as_uint(sE[(r + 8) * 68 + k8 * 8 + t4 + 4]);
#pragma unroll
            for (int nt = 0; nt < 8; nt++)
                mma_tf32(acc2[mt][nt], af, bf[nt]);
        }
    }

    // ---- epilogue: + gcn_b, store support ----
#pragma unroll
    for (int nt = 0; nt < 8; nt++) {
        int col   = nt * 8 + 2 * t4;
        float bb0 = gb[col];
        float bb1 = gb[col + 1];
#pragma unroll
        for (int mt = 0; mt < 2; mt++)
#pragma unroll
            for (int h = 0; h < 2; h++) {
                int gr = row0 + wrow + mt * 16 + h * 8 + g4;
                if (gr < nRows) {
                    *reinterpret_cast<float2*>(out + (size_t)gr * 64 + col) =
                        make_float2(acc2[mt][nt][h * 2 + 0] + bb0,
                                    acc2[mt][nt][h * 2 + 1] + bb1);
                }
            }
    }
}

// ---------------------------------------------------------------------------
// Edge scatter: out[dst] += support[src] * w, 16 threads/edge (float4 each).
// support (51 MB) + out (51 MB) are L2-resident; v4 red cuts atomic op count.
// ---------------------------------------------------------------------------
__global__ void __launch_bounds__(256)
edge_kernel(const float* __restrict__ support, const int* __restrict__ src,
            const int* __restrict__ dst, const float* __restrict__ w,
            float* __restrict__ out, int E)
{
    int g   = blockIdx.x * 256 + threadIdx.x;
    int e   = g >> 4;
    int sub = g & 15;
    if (e >= E) return;
    int   s  = src[e];
    int   d  = dst[e];
    float wt = w[e];
    float4 v = *reinterpret_cast<const float4*>(support + (size_t)s * 64 + sub * 4);
    float* o = out + (size_t)d * 64 + sub * 4;
    asm volatile("red.global.add.v4.f32 [%0], {%1, %2, %3, %4};"
                 :: "l"(o), "f"(v.x * wt), "f"(v.y * wt),
                    "f"(v.z * wt), "f"(v.w * wt)
                 : "memory");
}

// ---------------------------------------------------------------------------
__global__ void __launch_bounds__(256)
zero_kernel(float4* __restrict__ out, int n4)
{
    int i = blockIdx.x * 256 + threadIdx.x;
    if (i < n4) out[i] = make_float4(0.f, 0.f, 0.f, 0.f);
}

__global__ void __launch_bounds__(256)
normalize_kernel(float* __restrict__ out, int N)
{
    int row  = blockIdx.x * 8 + (threadIdx.x >> 5);
    int lane = threadIdx.x & 31;
    if (row >= N) return;
    float* p = out + (size_t)row * 64;
    float2 v = *reinterpret_cast<float2*>(p + lane * 2);
    float ss = v.x * v.x + v.y * v.y;
#pragma unroll
    for (int o = 16; o > 0; o >>= 1) ss += __shfl_xor_sync(0xFFFFFFFFu, ss, o);
    float inv = 1.0f / fmaxf(sqrtf(ss), 1e-12f);
    v.x *= inv;
    v.y *= inv;
    *reinterpret_cast<float2*>(p + lane * 2) = v;
}

// ---------------------------------------------------------------------------
extern "C" void kernel_launch(void* const* d_in, const int* in_sizes, int n_in,
                              void* d_out, int out_size)
{
    const float* feat_a   = (const float*)d_in[0];
    const float* W_a      = (const float*)d_in[1];
    const float* b_a      = (const float*)d_in[2];
    const float* feat_b   = (const float*)d_in[3];
    const float* W_b      = (const float*)d_in[4];
    const float* b_b      = (const float*)d_in[5];
    const float* feat_c   = (const float*)d_in[6];
    const float* W_c      = (const float*)d_in[7];
    const float* b_c      = (const float*)d_in[8];
    const float* gcn_W    = (const float*)d_in[9];
    const float* gcn_b    = (const float*)d_in[10];
    const float* edge_w   = (const float*)d_in[11];
    const int*   edge_src = (const int*)d_in[12];
    const int*   edge_dst = (const int*)d_in[13];

    const int nA = in_sizes[0] / 512;
    const int nB = in_sizes[3] / 256;
    const int nC = in_sizes[6] / 128;
    const int N  = nA + nB + nC;
    const int E  = in_sizes[11];

    float* sup = nullptr;
    cudaGetSymbolAddress((void**)&sup, g_support);
    float* out = (float*)d_out;

    const int SMEM = 92160;
    cudaFuncSetAttribute(fused_enc_gcn<512>,
                         cudaFuncAttributeMaxDynamicSharedMemorySize, SMEM);
    cudaFuncSetAttribute(fused_enc_gcn<256>,
                         cudaFuncAttributeMaxDynamicSharedMemorySize, SMEM);
    cudaFuncSetAttribute(fused_enc_gcn<128>,
                         cudaFuncAttributeMaxDynamicSharedMemorySize, SMEM);

    // zero the accumulator (d_out is poisoned)
    {
        int n4 = N * 16;
        zero_kernel<<<(n4 + 255) / 256, 256>>>((float4*)out, n4);
    }

    // fused encoder + GCN -> g_support
    fused_enc_gcn<512><<<(nA + 255) / 256, 256, SMEM>>>(
        feat_a, W_a, b_a, gcn_W, gcn_b, sup, nA);
    fused_enc_gcn<256><<<(nB + 255) / 256, 256, SMEM>>>(
        feat_b, W_b, b_b, gcn_W, gcn_b, sup + (size_t)nA * 64, nB);
    fused_enc_gcn<128><<<(nC + 255) / 256, 256, SMEM>>>(
        feat_c, W_c, b_c, gcn_W, gcn_b, sup + (size_t)(nA + nB) * 64, nC);

    // edge gather/scale/scatter-add into out
    {
        long long tot = (long long)E * 16;
        int blocks = (int)((tot + 255) / 256);
        edge_kernel<<<blocks, 256>>>(sup, edge_src, edge_dst, edge_w, out, E);
    }

    // row-wise L2 normalize in place
    normalize_kernel<<<(N + 7) / 8, 256>>>(out, N);
}